// round 7
// baseline (speedup 1.0000x reference)
#include <cuda_runtime.h>
#include <math_constants.h>

#define NOUT   257
#define NBATCH 32768
#define RPB    8

__device__ __forceinline__ void cmul(float ar, float ai, float br, float bi,
                                     float& cr, float& ci)
{
    cr = ar * br - ai * bi;
    ci = ar * bi + ai * br;
}

// One warp computes the 512-pt RFFT of one row.
// z[m]=0.5(x[2m]+ix[2m+1]); Z=FFT_256(z) via m = beta + 32*alpha:
//   step A: DFT_8 over alpha (in-reg)      -> G[k2][beta], k2 in br3 slots
//   step B: twiddle W_256^{beta*k2}
//   step C: FFT_32 over beta = b1 + 8*b2, k1 = c + 4*d:
//     T1(smem) -> DFT_4 over b2 -> twiddle W_32^{b1 c}
//     T2(smem) -> DFT_8 over b1 (-> d in br3 slots)
//     T3(smem) -> untangle pairs (k, 256-k) + coalesced store
__global__ __launch_bounds__(256)
void rfft512_warp(const float* __restrict__ x,
                  float* __restrict__ yre,
                  float* __restrict__ yim)
{
    __shared__ float2 bufA[RPB][284];   // T1 (36*k2+beta), reused for T3 (33*d + k2+8c)
    __shared__ float2 bufB[RPB][264];   // T2 (33*b1 + 4*k2 + c)

    const int lane = threadIdx.x & 31;
    const int w    = threadIdx.x >> 5;
    const long long row = (long long)blockIdx.x * RPB + w;
    const float* xr = x + row * 512;
    float2* A = bufA[w];
    float2* B = bufB[w];

    // ---- load z[m] = 0.5*(x[2m] + i x[2m+1]), m = lane + 32 r ----
    float zr[8], zi[8];
    #pragma unroll
    for (int r = 0; r < 8; ++r) {
        float2 v = *reinterpret_cast<const float2*>(xr + 2 * (lane + 32 * r));
        zr[r] = 0.5f * v.x; zi[r] = 0.5f * v.y;
    }

    // ---- step A: radix-8 DIF over reg index -> slot r holds k2 = br3(r) ----
    const float C = 0.70710678118654752440f;
    {   // h=4, twiddles W8^{0..3}
        float dr, di;
        dr = zr[0] - zr[4]; di = zi[0] - zi[4];
        zr[0] += zr[4]; zi[0] += zi[4];
        zr[4] = dr; zi[4] = di;

        dr = zr[1] - zr[5]; di = zi[1] - zi[5];
        zr[1] += zr[5]; zi[1] += zi[5];
        zr[5] = C * (dr + di); zi[5] = C * (di - dr);

        dr = zr[2] - zr[6]; di = zi[2] - zi[6];
        zr[2] += zr[6]; zi[2] += zi[6];
        zr[6] = di; zi[6] = -dr;

        dr = zr[3] - zr[7]; di = zi[3] - zi[7];
        zr[3] += zr[7]; zi[3] += zi[7];
        zr[7] = C * (di - dr); zi[7] = -C * (dr + di);
    }
    {   // h=2, twiddles 1, -i
        float dr, di;
        dr = zr[0] - zr[2]; di = zi[0] - zi[2];
        zr[0] += zr[2]; zi[0] += zi[2]; zr[2] = dr; zi[2] = di;

        dr = zr[1] - zr[3]; di = zi[1] - zi[3];
        zr[1] += zr[3]; zi[1] += zi[3]; zr[3] = di; zi[3] = -dr;

        dr = zr[4] - zr[6]; di = zi[4] - zi[6];
        zr[4] += zr[6]; zi[4] += zi[6]; zr[6] = dr; zi[6] = di;

        dr = zr[5] - zr[7]; di = zi[5] - zi[7];
        zr[5] += zr[7]; zi[5] += zi[7]; zr[7] = di; zi[7] = -dr;
    }
    {   // h=1
        float dr, di;
        dr = zr[0] - zr[1]; di = zi[0] - zi[1];
        zr[0] += zr[1]; zi[0] += zi[1]; zr[1] = dr; zi[1] = di;
        dr = zr[2] - zr[3]; di = zi[2] - zi[3];
        zr[2] += zr[3]; zi[2] += zi[3]; zr[3] = dr; zi[3] = di;
        dr = zr[4] - zr[5]; di = zi[4] - zi[5];
        zr[4] += zr[5]; zi[4] += zi[5]; zr[5] = dr; zi[5] = di;
        dr = zr[6] - zr[7]; di = zi[6] - zi[7];
        zr[6] += zr[7]; zi[6] += zi[7]; zr[7] = dr; zi[7] = di;
    }

    // ---- step B: multiply slot (k2) by W_256^{lane * k2} ----
    {
        float w1r, w1i;
        __sincosf(-2.0f * CUDART_PI_F * (float)lane / 256.0f, &w1i, &w1r);
        float w2r, w2i, w3r, w3i, w4r, w4i, w5r, w5i, w6r, w6i, w7r, w7i;
        cmul(w1r, w1i, w1r, w1i, w2r, w2i);
        cmul(w2r, w2i, w1r, w1i, w3r, w3i);
        cmul(w2r, w2i, w2r, w2i, w4r, w4i);
        cmul(w4r, w4i, w1r, w1i, w5r, w5i);
        cmul(w3r, w3i, w3r, w3i, w6r, w6i);
        cmul(w4r, w4i, w3r, w3i, w7r, w7i);

        float tr, ti;
        cmul(zr[1], zi[1], w4r, w4i, tr, ti); zr[1] = tr; zi[1] = ti;  // k2=4
        cmul(zr[2], zi[2], w2r, w2i, tr, ti); zr[2] = tr; zi[2] = ti;  // k2=2
        cmul(zr[3], zi[3], w6r, w6i, tr, ti); zr[3] = tr; zi[3] = ti;  // k2=6
        cmul(zr[4], zi[4], w1r, w1i, tr, ti); zr[4] = tr; zi[4] = ti;  // k2=1
        cmul(zr[5], zi[5], w5r, w5i, tr, ti); zr[5] = tr; zi[5] = ti;  // k2=5
        cmul(zr[6], zi[6], w3r, w3i, tr, ti); zr[6] = tr; zi[6] = ti;  // k2=3
        cmul(zr[7], zi[7], w7r, w7i, tr, ti); zr[7] = tr; zi[7] = ti;  // k2=7
    }

    // ---- T1: write G[k2][lane] at 36*k2 + lane (conflict-free) ----
    {
        const int K2M[8] = {0, 4, 2, 6, 1, 5, 3, 7};
        #pragma unroll
        for (int r = 0; r < 8; ++r)
            A[36 * K2M[r] + lane] = make_float2(zr[r], zi[r]);
    }
    __syncwarp();

    // ---- P2: thread (b1,g) handles k2 = 2g+e; DFT_4 over b2 + W_32^{b1 c} ----
    const int b1 = lane & 7;
    const int g  = lane >> 3;
    float fr[2][4], fi[2][4];
    #pragma unroll
    for (int e = 0; e < 2; ++e) {
        const int base = 36 * (2 * g + e) + b1;
        const float2 q0 = A[base];
        const float2 q1 = A[base + 8];
        const float2 q2 = A[base + 16];
        const float2 q3 = A[base + 24];
        const float t0r = q0.x + q2.x, t0i = q0.y + q2.y;
        const float t1r = q0.x - q2.x, t1i = q0.y - q2.y;
        const float t2r = q1.x + q3.x, t2i = q1.y + q3.y;
        const float t3r = q1.x - q3.x, t3i = q1.y - q3.y;
        fr[e][0] = t0r + t2r; fi[e][0] = t0i + t2i;
        fr[e][2] = t0r - t2r; fi[e][2] = t0i - t2i;
        fr[e][1] = t1r + t3i; fi[e][1] = t1i - t3r;   // t1 - i*t3
        fr[e][3] = t1r - t3i; fi[e][3] = t1i + t3r;   // t1 + i*t3
    }
    {
        float w1r, w1i;    // W_32^{b1}
        __sincosf(-CUDART_PI_F * (float)b1 / 16.0f, &w1i, &w1r);
        const float w2r = w1r * w1r - w1i * w1i, w2i = 2.0f * w1r * w1i;
        float w3r, w3i; cmul(w2r, w2i, w1r, w1i, w3r, w3i);
        #pragma unroll
        for (int e = 0; e < 2; ++e) {
            float tr, ti;
            cmul(fr[e][1], fi[e][1], w1r, w1i, tr, ti); fr[e][1] = tr; fi[e][1] = ti;
            cmul(fr[e][2], fi[e][2], w2r, w2i, tr, ti); fr[e][2] = tr; fi[e][2] = ti;
            cmul(fr[e][3], fi[e][3], w3r, w3i, tr, ti); fr[e][3] = tr; fi[e][3] = ti;
        }
    }
    // ---- T2: write H[k2][b1][c] at 33*b1 + 4*k2 + c (conflict-free) ----
    #pragma unroll
    for (int e = 0; e < 2; ++e)
        #pragma unroll
        for (int c = 0; c < 4; ++c)
            B[33 * b1 + 8 * g + 4 * e + c] = make_float2(fr[e][c], fi[e][c]);
    __syncwarp();

    // ---- P3: thread u=lane (k2=u>>2, c=u&3): read over b1, DFT_8 over b1 ----
    float hr[8], hi[8];
    #pragma unroll
    for (int b = 0; b < 8; ++b) {          // 4*k2 + c == lane
        const float2 v = B[33 * b + lane];
        hr[b] = v.x; hi[b] = v.y;
    }
    {   // DFT_8 (DIF cascade), output slot s holds d = br3(s)
        float dr, di;
        // h=4
        dr = hr[0] - hr[4]; di = hi[0] - hi[4];
        hr[0] += hr[4]; hi[0] += hi[4];
        hr[4] = dr; hi[4] = di;
        dr = hr[1] - hr[5]; di = hi[1] - hi[5];
        hr[1] += hr[5]; hi[1] += hi[5];
        hr[5] = C * (dr + di); hi[5] = C * (di - dr);
        dr = hr[2] - hr[6]; di = hi[2] - hi[6];
        hr[2] += hr[6]; hi[2] += hi[6];
        hr[6] = di; hi[6] = -dr;
        dr = hr[3] - hr[7]; di = hi[3] - hi[7];
        hr[3] += hr[7]; hi[3] += hi[7];
        hr[7] = C * (di - dr); hi[7] = -C * (dr + di);
        // h=2
        dr = hr[0] - hr[2]; di = hi[0] - hi[2];
        hr[0] += hr[2]; hi[0] += hi[2]; hr[2] = dr; hi[2] = di;
        dr = hr[1] - hr[3]; di = hi[1] - hi[3];
        hr[1] += hr[3]; hi[1] += hi[3]; hr[3] = di; hi[3] = -dr;
        dr = hr[4] - hr[6]; di = hi[4] - hi[6];
        hr[4] += hr[6]; hi[4] += hi[6]; hr[6] = dr; hi[6] = di;
        dr = hr[5] - hr[7]; di = hi[5] - hi[7];
        hr[5] += hr[7]; hi[5] += hi[7]; hr[7] = di; hi[7] = -dr;
        // h=1
        dr = hr[0] - hr[1]; di = hi[0] - hi[1];
        hr[0] += hr[1]; hi[0] += hi[1]; hr[1] = dr; hi[1] = di;
        dr = hr[2] - hr[3]; di = hi[2] - hi[3];
        hr[2] += hr[3]; hi[2] += hi[3]; hr[3] = dr; hi[3] = di;
        dr = hr[4] - hr[5]; di = hi[4] - hi[5];
        hr[4] += hr[5]; hi[4] += hi[5]; hr[5] = dr; hi[5] = di;
        dr = hr[6] - hr[7]; di = hi[6] - hi[7];
        hr[6] += hr[7]; hi[6] += hi[7]; hr[7] = dr; hi[7] = di;
    }
    // ---- T3: Z[k2 + 8c + 32d] at 33*d + (k2 + 8c); reuse bufA ----
    {
        const int K2M[8] = {0, 4, 2, 6, 1, 5, 3, 7};
        const int vkc = (lane >> 2) + ((lane & 3) << 3);   // k2 + 8c
        #pragma unroll
        for (int s = 0; s < 8; ++s)
            A[33 * K2M[s] + vkc] = make_float2(hr[s], hi[s]);
    }
    __syncwarp();

    // ---- untangle X[k] = Fe + W_512^k Fo, k = 32j + lane; coalesced store ----
    float* orow = yre + row * NOUT;
    float* irow = yim + row * NOUT;
    {
        float bc, bs;   // W_512^lane
        __sincosf(-2.0f * CUDART_PI_F * (float)lane / 512.0f, &bs, &bc);
        const int lanem = (32 - lane) & 31;

        // W_16^j = (CJ, SJ)
        const float CJ[8] = { 1.0f,  0.92387953251128674f,  0.70710678118654757f,
                              0.38268343236508984f, 0.0f, -0.38268343236508973f,
                             -0.70710678118654746f, -0.92387953251128674f};
        const float SJ[8] = { 0.0f, -0.38268343236508977f, -0.70710678118654746f,
                             -0.92387953251128674f, -1.0f, -0.92387953251128674f,
                             -0.70710678118654757f, -0.38268343236508989f};

        #pragma unroll
        for (int j = 0; j < 8; ++j) {
            const float2 Zk = A[33 * j + lane];
            const int jm = lane ? (7 - j) : ((8 - j) & 7);
            const float2 Zm = A[33 * jm + lanem];

            const float Fer = Zk.x + Zm.x;
            const float Fei = Zk.y - Zm.y;
            const float For = Zk.y + Zm.y;
            const float Foi = Zm.x - Zk.x;

            // w = W_512^{32j + lane} = base * W_16^j
            const float wc = fmaf(bc, CJ[j], -bs * SJ[j]);
            const float ws = fmaf(bc, SJ[j],  bs * CJ[j]);

            const int k = 32 * j + lane;
            orow[k] = fmaf(wc, For, fmaf(-ws, Foi, Fer));
            irow[k] = fmaf(wc, Foi, fmaf( ws, For, Fei));
        }
        if (lane == 0) {   // X[256] = Re(Z0) - Im(Z0); buffer holds 0.5*Z
            const float2 Z0 = A[0];
            orow[256] = 2.0f * (Z0.x - Z0.y);
            irow[256] = 0.0f;
        }
    }
}

extern "C" void kernel_launch(void* const* d_in, const int* in_sizes, int n_in,
                              void* d_out, int out_size)
{
    const float* x = (const float*)d_in[0];
    float* out = (float*)d_out;
    float* yre = out;                                  // [32768, 257]
    float* yim = out + (long long)NBATCH * NOUT;       // [32768, 257]

    rfft512_warp<<<NBATCH / RPB, 32 * RPB>>>(x, yre, yim);
}

// round 8
// speedup vs baseline: 1.0051x; 1.0051x over previous
#include <cuda_runtime.h>
#include <math_constants.h>

#define NOUT   257
#define NBATCH 32768
#define RPB    8

__device__ __forceinline__ void cmul(float ar, float ai, float br, float bi,
                                     float& cr, float& ci)
{
    cr = ar * br - ai * bi;
    ci = ar * bi + ai * br;
}

// Swap lane-bit (H) with slot-bit 2 (slots c <-> c+4), then register-local
// DIF butterfly over slot pairs with per-thread-uniform twiddle (twc,tws).
template<int H>
__device__ __forceinline__ void swap_bfly(float* zr, float* zi, int lane,
                                          float twc, float tws)
{
    const bool hi = (lane & H) != 0;
    #pragma unroll
    for (int c = 0; c < 4; ++c) {
        const float sr_ = hi ? zr[c] : zr[c + 4];
        const float si_ = hi ? zi[c] : zi[c + 4];
        const float rr = __shfl_xor_sync(0xffffffffu, sr_, H);
        const float ri = __shfl_xor_sync(0xffffffffu, si_, H);
        if (hi) { zr[c] = rr; zi[c] = ri; }
        else    { zr[c + 4] = rr; zi[c + 4] = ri; }
    }
    #pragma unroll
    for (int c = 0; c < 4; ++c) {
        const float dr = zr[c] - zr[c + 4];
        const float di = zi[c] - zi[c + 4];
        zr[c] += zr[c + 4]; zi[c] += zi[c + 4];
        zr[c + 4] = fmaf(dr, twc, -di * tws);
        zi[c + 4] = fmaf(di, twc,  dr * tws);
    }
}

__global__ __launch_bounds__(256)
void rfft512_warp(const float* __restrict__ x,
                  float* __restrict__ yre,
                  float* __restrict__ yim)
{
    // Z staged as scalars at addr = k + 2*(k>>5): conflict-free writes & reads.
    __shared__ float ssr[RPB][272];
    __shared__ float ssi[RPB][272];

    const int lane = threadIdx.x & 31;
    const int w    = threadIdx.x >> 5;
    const long long row = (long long)blockIdx.x * RPB + w;
    const float* xr = x + row * 512;
    float* sr = ssr[w];
    float* si = ssi[w];

    // ---- load z[m] = 0.5*(x[2m] + i x[2m+1]), m = lane + 32 r ----
    float zr[8], zi[8];
    #pragma unroll
    for (int r = 0; r < 8; ++r) {
        float2 v = *reinterpret_cast<const float2*>(xr + 2 * (lane + 32 * r));
        zr[r] = 0.5f * v.x; zi[r] = 0.5f * v.y;
    }

    // ---- step A: radix-8 DIF over reg index -> slot r holds k2 = br3(r) ----
    const float C = 0.70710678118654752440f;
    {   // h=4, twiddles W8^{0..3}
        float dr, di;
        dr = zr[0] - zr[4]; di = zi[0] - zi[4];
        zr[0] += zr[4]; zi[0] += zi[4];
        zr[4] = dr; zi[4] = di;

        dr = zr[1] - zr[5]; di = zi[1] - zi[5];
        zr[1] += zr[5]; zi[1] += zi[5];
        zr[5] = C * (dr + di); zi[5] = C * (di - dr);

        dr = zr[2] - zr[6]; di = zi[2] - zi[6];
        zr[2] += zr[6]; zi[2] += zi[6];
        zr[6] = di; zi[6] = -dr;

        dr = zr[3] - zr[7]; di = zi[3] - zi[7];
        zr[3] += zr[7]; zi[3] += zi[7];
        zr[7] = C * (di - dr); zi[7] = -C * (dr + di);
    }
    {   // h=2, twiddles 1, -i
        float dr, di;
        dr = zr[0] - zr[2]; di = zi[0] - zi[2];
        zr[0] += zr[2]; zi[0] += zi[2]; zr[2] = dr; zi[2] = di;

        dr = zr[1] - zr[3]; di = zi[1] - zi[3];
        zr[1] += zr[3]; zi[1] += zi[3]; zr[3] = di; zi[3] = -dr;

        dr = zr[4] - zr[6]; di = zi[4] - zi[6];
        zr[4] += zr[6]; zi[4] += zi[6]; zr[6] = dr; zi[6] = di;

        dr = zr[5] - zr[7]; di = zi[5] - zi[7];
        zr[5] += zr[7]; zi[5] += zi[7]; zr[7] = di; zi[7] = -dr;
    }
    {   // h=1
        float dr, di;
        dr = zr[0] - zr[1]; di = zi[0] - zi[1];
        zr[0] += zr[1]; zi[0] += zi[1]; zr[1] = dr; zi[1] = di;
        dr = zr[2] - zr[3]; di = zi[2] - zi[3];
        zr[2] += zr[3]; zi[2] += zi[3]; zr[3] = dr; zi[3] = di;
        dr = zr[4] - zr[5]; di = zi[4] - zi[5];
        zr[4] += zr[5]; zi[4] += zi[5]; zr[5] = dr; zi[5] = di;
        dr = zr[6] - zr[7]; di = zi[6] - zi[7];
        zr[6] += zr[7]; zi[6] += zi[7]; zr[7] = dr; zi[7] = di;
    }

    // ---- step B: multiply slot (k2 = br3(slot)) by W_256^{lane * k2} ----
    {
        float w1r, w1i;
        __sincosf(-2.0f * CUDART_PI_F * (float)lane / 256.0f, &w1i, &w1r);
        float w2r, w2i, w3r, w3i, w4r, w4i, w5r, w5i, w6r, w6i, w7r, w7i;
        cmul(w1r, w1i, w1r, w1i, w2r, w2i);
        cmul(w2r, w2i, w1r, w1i, w3r, w3i);
        cmul(w2r, w2i, w2r, w2i, w4r, w4i);
        cmul(w4r, w4i, w1r, w1i, w5r, w5i);
        cmul(w3r, w3i, w3r, w3i, w6r, w6i);
        cmul(w4r, w4i, w3r, w3i, w7r, w7i);

        float tr, ti;
        cmul(zr[1], zi[1], w4r, w4i, tr, ti); zr[1] = tr; zi[1] = ti;  // k2=4
        cmul(zr[2], zi[2], w2r, w2i, tr, ti); zr[2] = tr; zi[2] = ti;  // k2=2
        cmul(zr[3], zi[3], w6r, w6i, tr, ti); zr[3] = tr; zi[3] = ti;  // k2=6
        cmul(zr[4], zi[4], w1r, w1i, tr, ti); zr[4] = tr; zi[4] = ti;  // k2=1
        cmul(zr[5], zi[5], w5r, w5i, tr, ti); zr[5] = tr; zi[5] = ti;  // k2=5
        cmul(zr[6], zi[6], w3r, w3i, tr, ti); zr[6] = tr; zi[6] = ti;  // k2=3
        cmul(zr[7], zi[7], w7r, w7i, tr, ti); zr[7] = tr; zi[7] = ti;  // k2=7
    }

    // ---- step C: 32-pt FFT over lanes via lane-bit <-> slot-bit swaps ----
    {
        float t1c, t1s;   // tw1 = W_32^{lane & 15}
        __sincosf(-CUDART_PI_F * (float)(lane & 15) / 16.0f, &t1s, &t1c);
        // tw2 = (-1)^{l3} * tw1^2 = W_16^{lane & 7}
        float t2c = t1c * t1c - t1s * t1s, t2s = 2.0f * t1c * t1s;
        if (lane & 8) { t2c = -t2c; t2s = -t2s; }
        // tw3 = (-1)^{l2} * tw2^2 = W_8^{lane & 3}
        float t3c = t2c * t2c - t2s * t2s, t3s = 2.0f * t2c * t2s;
        if (lane & 4) { t3c = -t3c; t3s = -t3s; }

        swap_bfly<16>(zr, zi, lane, t1c, t1s);   // n4 -> kappa0
        swap_bfly<8>(zr, zi, lane, t2c, t2s);    // n3 -> kappa1
        swap_bfly<4>(zr, zi, lane, t3c, t3s);    // n2 -> kappa2

        {   // H=2 swap, twiddle tw4 = (lane&1) ? -i : 1 (select, no mul)
            const bool hi = (lane & 2) != 0;
            #pragma unroll
            for (int c = 0; c < 4; ++c) {
                const float sr_ = hi ? zr[c] : zr[c + 4];
                const float si_ = hi ? zi[c] : zi[c + 4];
                const float rr = __shfl_xor_sync(0xffffffffu, sr_, 2);
                const float ri = __shfl_xor_sync(0xffffffffu, si_, 2);
                if (hi) { zr[c] = rr; zi[c] = ri; }
                else    { zr[c + 4] = rr; zi[c + 4] = ri; }
            }
            const bool neg = (lane & 1) != 0;
            #pragma unroll
            for (int c = 0; c < 4; ++c) {
                const float dr = zr[c] - zr[c + 4];
                const float di = zi[c] - zi[c + 4];
                zr[c] += zr[c + 4]; zi[c] += zi[c + 4];
                zr[c + 4] = neg ?  di : dr;      // *(−i) on odd lanes
                zi[c + 4] = neg ? -dr : di;
            }
        }
        {   // H=1 swap, twiddle-free butterfly
            const bool hi = (lane & 1) != 0;
            #pragma unroll
            for (int c = 0; c < 4; ++c) {
                const float sr_ = hi ? zr[c] : zr[c + 4];
                const float si_ = hi ? zi[c] : zi[c + 4];
                const float rr = __shfl_xor_sync(0xffffffffu, sr_, 1);
                const float ri = __shfl_xor_sync(0xffffffffu, si_, 1);
                if (hi) { zr[c] = rr; zi[c] = ri; }
                else    { zr[c + 4] = rr; zi[c + 4] = ri; }
            }
            #pragma unroll
            for (int c = 0; c < 4; ++c) {
                const float dr = zr[c] - zr[c + 4];
                const float di = zi[c] - zi[c + 4];
                zr[c] += zr[c + 4]; zi[c] += zi[c + 4];
                zr[c + 4] = dr; zi[c + 4] = di;
            }
        }
    }
    // slot c on lane l holds Z[k]:
    // k = l4 + 8*l3 + 16*l2 + 32*l1 + 64*l0 + 4*(c&1) + 2*((c>>1)&1) + 128*((c>>2)&1)

    // ---- stage Z into smem at addr = k + 2*(k>>5) (conflict-free) ----
    {
        const int P = ((lane >> 4) & 1) + (((lane >> 3) & 1) << 3)
                    + (((lane >> 2) & 1) << 4) + (((lane >> 1) & 1) << 5)
                    + ((lane & 1) << 6);
        const int KC[8] = {0, 4, 2, 6, 128, 132, 130, 134};
        #pragma unroll
        for (int c = 0; c < 8; ++c) {
            const int k = P + KC[c];
            const int a = k + 2 * (k >> 5);
            sr[a] = zr[c]; si[a] = zi[c];
        }
    }
    __syncwarp();

    // ---- untangle X[k] = Fe + W_512^k Fo, k = 32j + lane; coalesced store ----
    float* orow = yre + row * NOUT;
    float* irow = yim + row * NOUT;
    {
        float bc, bs;   // W_512^lane
        __sincosf(-2.0f * CUDART_PI_F * (float)lane / 512.0f, &bs, &bc);
        const int lanem = (32 - lane) & 31;

        // W_16^j = (CJ, SJ)
        const float CJ[8] = { 1.0f,  0.92387953251128674f,  0.70710678118654757f,
                              0.38268343236508984f, 0.0f, -0.38268343236508973f,
                             -0.70710678118654746f, -0.92387953251128674f};
        const float SJ[8] = { 0.0f, -0.38268343236508977f, -0.70710678118654746f,
                             -0.92387953251128674f, -1.0f, -0.92387953251128674f,
                             -0.70710678118654757f, -0.38268343236508989f};

        #pragma unroll
        for (int j = 0; j < 8; ++j) {
            const int a = 34 * j + lane;                 // k=32j+lane
            const float Zkr = sr[a], Zki = si[a];
            const int jm = lane ? (7 - j) : ((8 - j) & 7);
            const int am = 34 * jm + lanem;              // k' = 256-k (mod 256)
            const float Zmr = sr[am], Zmi = si[am];

            const float Fer = Zkr + Zmr;
            const float Fei = Zki - Zmi;
            const float For = Zki + Zmi;
            const float Foi = Zmr - Zkr;

            // w = W_512^{32j + lane} = base * W_16^j
            const float wc = fmaf(bc, CJ[j], -bs * SJ[j]);
            const float ws = fmaf(bc, SJ[j],  bs * CJ[j]);

            const int k = 32 * j + lane;
            orow[k] = fmaf(wc, For, fmaf(-ws, Foi, Fer));
            irow[k] = fmaf(wc, Foi, fmaf( ws, For, Fei));
        }
        if (lane == 0) {   // X[256] = Re(Z0) - Im(Z0); buffer holds 0.5*Z
            orow[256] = 2.0f * (sr[0] - si[0]);
            irow[256] = 0.0f;
        }
    }
}

extern "C" void kernel_launch(void* const* d_in, const int* in_sizes, int n_in,
                              void* d_out, int out_size)
{
    const float* x = (const float*)d_in[0];
    float* out = (float*)d_out;
    float* yre = out;                                  // [32768, 257]
    float* yim = out + (long long)NBATCH * NOUT;       // [32768, 257]

    rfft512_warp<<<NBATCH / RPB, 32 * RPB>>>(x, yre, yim);
}

// round 9
// speedup vs baseline: 1.0632x; 1.0577x over previous
#include <cuda_runtime.h>
#include <math_constants.h>
#include <cstdint>

#define NOUT   257
#define NBATCH 32768
#define RPB    8

__device__ __forceinline__ void cmul(float ar, float ai, float br, float bi,
                                     float& cr, float& ci)
{
    cr = ar * br - ai * bi;
    ci = ar * bi + ai * br;
}

// ---- f32x2 packed helpers (sm_103a native) ----
__device__ __forceinline__ uint64_t pk2(float lo, float hi) {
    uint64_t r;
    asm("mov.b64 %0, {%1, %2};" : "=l"(r) : "f"(lo), "f"(hi));
    return r;
}
__device__ __forceinline__ void upk2(uint64_t v, float& lo, float& hi) {
    asm("mov.b64 {%0, %1}, %2;" : "=f"(lo), "=f"(hi) : "l"(v));
}
__device__ __forceinline__ uint64_t fma2(uint64_t a, uint64_t b, uint64_t c) {
    uint64_t d;
    asm("fma.rn.f32x2 %0, %1, %2, %3;" : "=l"(d) : "l"(a), "l"(b), "l"(c));
    return d;
}
__device__ __forceinline__ uint64_t mul2(uint64_t a, uint64_t b) {
    uint64_t d;
    asm("mul.rn.f32x2 %0, %1, %2;" : "=l"(d) : "l"(a), "l"(b));
    return d;
}

#define ONE2  0x3F8000003F800000ull   // ( 1.0f,  1.0f)
#define NEG2  0xBF800000BF800000ull   // (-1.0f, -1.0f)

// Packed cross-lane DIF stage, butterfly distance H (select-free).
template<int H>
__device__ __forceinline__ void dif_stage_p(uint64_t* Zr, uint64_t* Zi,
                                            uint64_t s2, uint64_t wc2,
                                            uint64_t nws2, uint64_t ws2)
{
    #pragma unroll
    for (int q = 0; q < 4; ++q) {
        const uint64_t orr = __shfl_xor_sync(0xffffffffu, Zr[q], H);
        const uint64_t oii = __shfl_xor_sync(0xffffffffu, Zi[q], H);
        const uint64_t dr = fma2(s2, Zr[q], orr);
        const uint64_t di = fma2(s2, Zi[q], oii);
        Zr[q] = fma2(wc2, dr, mul2(nws2, di));
        Zi[q] = fma2(wc2, di, mul2(ws2,  dr));
    }
}

__global__ __launch_bounds__(256)
void rfft512_warp(const float* __restrict__ x,
                  float* __restrict__ yre,
                  float* __restrict__ yim)
{
    // Z staged as scalars at addr = k + 3*(k>>5): conflict-free scatter/gather.
    __shared__ float ssr[RPB][284];
    __shared__ float ssi[RPB][284];

    const int lane = threadIdx.x & 31;
    const int w    = threadIdx.x >> 5;
    const long long row = (long long)blockIdx.x * RPB + w;
    const float* xr = x + row * 512;
    float* sr = ssr[w];
    float* si = ssi[w];

    // ---- load z[m] = 0.5*(x[2m] + i x[2m+1]), m = lane + 32 r ----
    float zr[8], zi[8];
    #pragma unroll
    for (int r = 0; r < 8; ++r) {
        float2 v = *reinterpret_cast<const float2*>(xr + 2 * (lane + 32 * r));
        zr[r] = 0.5f * v.x; zi[r] = 0.5f * v.y;
    }

    // ---- step A: radix-8 DIF over reg index -> slot r holds k2 = br3(r) ----
    const float C = 0.70710678118654752440f;
    {   // h=4, twiddles W8^{0..3}
        float dr, di;
        dr = zr[0] - zr[4]; di = zi[0] - zi[4];
        zr[0] += zr[4]; zi[0] += zi[4];
        zr[4] = dr; zi[4] = di;

        dr = zr[1] - zr[5]; di = zi[1] - zi[5];
        zr[1] += zr[5]; zi[1] += zi[5];
        zr[5] = C * (dr + di); zi[5] = C * (di - dr);

        dr = zr[2] - zr[6]; di = zi[2] - zi[6];
        zr[2] += zr[6]; zi[2] += zi[6];
        zr[6] = di; zi[6] = -dr;

        dr = zr[3] - zr[7]; di = zi[3] - zi[7];
        zr[3] += zr[7]; zi[3] += zi[7];
        zr[7] = C * (di - dr); zi[7] = -C * (dr + di);
    }
    {   // h=2, twiddles 1, -i
        float dr, di;
        dr = zr[0] - zr[2]; di = zi[0] - zi[2];
        zr[0] += zr[2]; zi[0] += zi[2]; zr[2] = dr; zi[2] = di;

        dr = zr[1] - zr[3]; di = zi[1] - zi[3];
        zr[1] += zr[3]; zi[1] += zi[3]; zr[3] = di; zi[3] = -dr;

        dr = zr[4] - zr[6]; di = zi[4] - zi[6];
        zr[4] += zr[6]; zi[4] += zi[6]; zr[6] = dr; zi[6] = di;

        dr = zr[5] - zr[7]; di = zi[5] - zi[7];
        zr[5] += zr[7]; zi[5] += zi[7]; zr[7] = di; zi[7] = -dr;
    }
    {   // h=1
        float dr, di;
        dr = zr[0] - zr[1]; di = zi[0] - zi[1];
        zr[0] += zr[1]; zi[0] += zi[1]; zr[1] = dr; zi[1] = di;
        dr = zr[2] - zr[3]; di = zi[2] - zi[3];
        zr[2] += zr[3]; zi[2] += zi[3]; zr[3] = dr; zi[3] = di;
        dr = zr[4] - zr[5]; di = zi[4] - zi[5];
        zr[4] += zr[5]; zi[4] += zi[5]; zr[5] = dr; zi[5] = di;
        dr = zr[6] - zr[7]; di = zi[6] - zi[7];
        zr[6] += zr[7]; zi[6] += zi[7]; zr[7] = dr; zi[7] = di;
    }

    // ---- step B: multiply slot (k2) by W_256^{lane * k2} ----
    {
        float w1r, w1i;
        __sincosf(-2.0f * CUDART_PI_F * (float)lane / 256.0f, &w1i, &w1r);
        float w2r, w2i, w3r, w3i, w4r, w4i, w5r, w5i, w6r, w6i, w7r, w7i;
        cmul(w1r, w1i, w1r, w1i, w2r, w2i);
        cmul(w2r, w2i, w1r, w1i, w3r, w3i);
        cmul(w2r, w2i, w2r, w2i, w4r, w4i);
        cmul(w4r, w4i, w1r, w1i, w5r, w5i);
        cmul(w3r, w3i, w3r, w3i, w6r, w6i);
        cmul(w4r, w4i, w3r, w3i, w7r, w7i);

        float tr, ti;
        cmul(zr[1], zi[1], w4r, w4i, tr, ti); zr[1] = tr; zi[1] = ti;  // k2=4
        cmul(zr[2], zi[2], w2r, w2i, tr, ti); zr[2] = tr; zi[2] = ti;  // k2=2
        cmul(zr[3], zi[3], w6r, w6i, tr, ti); zr[3] = tr; zi[3] = ti;  // k2=6
        cmul(zr[4], zi[4], w1r, w1i, tr, ti); zr[4] = tr; zi[4] = ti;  // k2=1
        cmul(zr[5], zi[5], w5r, w5i, tr, ti); zr[5] = tr; zi[5] = ti;  // k2=5
        cmul(zr[6], zi[6], w3r, w3i, tr, ti); zr[6] = tr; zi[6] = ti;  // k2=3
        cmul(zr[7], zi[7], w7r, w7i, tr, ti); zr[7] = tr; zi[7] = ti;  // k2=7
    }

    // ---- step C: 32-pt DIF across lanes, f32x2-packed over reg pairs ----
    {
        float uc, us;   // u = W_32^{lane&15}
        __sincosf(-CUDART_PI_F * (float)(lane & 15) / 16.0f, &us, &uc);
        const float p2c = uc * uc - us * us,     p2s = 2.0f * uc * us;
        const float p4c = p2c * p2c - p2s * p2s, p4s = 2.0f * p2c * p2s;
        const float p8c = p4c * p4c - p4s * p4s, p8s = 2.0f * p4c * p4s;

        uint64_t Zr[4], Zi[4];
        #pragma unroll
        for (int q = 0; q < 4; ++q) {
            Zr[q] = pk2(zr[2 * q], zr[2 * q + 1]);
            Zi[q] = pk2(zi[2 * q], zi[2 * q + 1]);
        }

        {   // H=16: w = u
            const bool hi = (lane & 16) != 0;
            const float wc = hi ?  uc : 1.0f;
            const float ws = hi ?  us : 0.0f;
            dif_stage_p<16>(Zr, Zi, hi ? NEG2 : ONE2,
                            pk2(wc, wc), pk2(-ws, -ws), pk2(ws, ws));
        }
        {   // H=8: w = -u^2
            const bool hi = (lane & 8) != 0;
            const float wc = hi ? -p2c : 1.0f;
            const float ws = hi ? -p2s : 0.0f;
            dif_stage_p<8>(Zr, Zi, hi ? NEG2 : ONE2,
                           pk2(wc, wc), pk2(-ws, -ws), pk2(ws, ws));
        }
        {   // H=4: w = -u^4
            const bool hi = (lane & 4) != 0;
            const float wc = hi ? -p4c : 1.0f;
            const float ws = hi ? -p4s : 0.0f;
            dif_stage_p<4>(Zr, Zi, hi ? NEG2 : ONE2,
                           pk2(wc, wc), pk2(-ws, -ws), pk2(ws, ws));
        }
        {   // H=2: w = -u^8
            const bool hi = (lane & 2) != 0;
            const float wc = hi ? -p8c : 1.0f;
            const float ws = hi ? -p8s : 0.0f;
            dif_stage_p<2>(Zr, Zi, hi ? NEG2 : ONE2,
                           pk2(wc, wc), pk2(-ws, -ws), pk2(ws, ws));
        }
        {   // H=1: w = 1 (twiddle-free)
            const uint64_t s2 = (lane & 1) ? NEG2 : ONE2;
            #pragma unroll
            for (int q = 0; q < 4; ++q) {
                const uint64_t orr = __shfl_xor_sync(0xffffffffu, Zr[q], 1);
                const uint64_t oii = __shfl_xor_sync(0xffffffffu, Zi[q], 1);
                Zr[q] = fma2(s2, Zr[q], orr);
                Zi[q] = fma2(s2, Zi[q], oii);
            }
        }

        #pragma unroll
        for (int q = 0; q < 4; ++q) {
            upk2(Zr[q], zr[2 * q], zr[2 * q + 1]);
            upk2(Zi[q], zi[2 * q], zi[2 * q + 1]);
        }
    }
    // lane l, slot r holds 0.5 * Z[k2 + 8*kappa], k2 = br3(r), kappa = br5(l)

    // ---- stage Z to smem at addr = k + 3*(k>>5)  (conflict-free scatter) ----
    {
        const int kap = __brev((unsigned)lane) >> 27;   // bitrev5(lane)
        const int base = 8 * kap + 3 * (kap >> 2);      // = (8kap) + 3*((8kap)>>5)
        const int K2M[8] = {0, 4, 2, 6, 1, 5, 3, 7};
        #pragma unroll
        for (int r = 0; r < 8; ++r) {
            sr[base + K2M[r]] = zr[r];
            si[base + K2M[r]] = zi[r];
        }
    }
    __syncwarp();

    // ---- pair untangle: k = 32j + lane (j=0..3) gives X[k] AND X[256-k] ----
    float* orow = yre + row * NOUT;
    float* irow = yim + row * NOUT;
    {
        float bc, bs;   // W_512^lane
        __sincosf(-2.0f * CUDART_PI_F * (float)lane / 512.0f, &bs, &bc);

        // W_16^j, j = 0..3
        const float CJ[4] = { 1.0f,  0.92387953251128674f,
                              0.70710678118654757f,  0.38268343236508984f};
        const float SJ[4] = { 0.0f, -0.38268343236508977f,
                             -0.70710678118654746f, -0.92387953251128674f};

        #pragma unroll
        for (int j = 0; j < 4; ++j) {
            const int k  = 32 * j + lane;
            const int ak = k + 3 * (k >> 5);
            const int km = (256 - k) & 255;           // Z partner (wraps k=0 -> 0)
            const int am = km + 3 * (km >> 5);

            const float Zkr = sr[ak], Zki = si[ak];
            const float Zmr = sr[am], Zmi = si[am];

            const float Fer = Zkr + Zmr;
            const float Fei = Zki - Zmi;
            const float For = Zki + Zmi;
            const float Foi = Zmr - Zkr;

            // w = W_512^k = (bc + i bs) * W_16^j
            const float wc = fmaf(bc, CJ[j], -bs * SJ[j]);
            const float ws = fmaf(bc, SJ[j],  bs * CJ[j]);

            const float P = fmaf(wc, For, -ws * Foi);
            const float Q = fmaf(wc, Foi,  ws * For);

            orow[k] = Fer + P;          // X[k]
            irow[k] = Fei + Q;
            orow[256 - k] = Fer - P;    // X[256-k] (k=0 -> bin 256)
            irow[256 - k] = Q - Fei;
        }
        if (lane == 0) {                // self-paired bin 128: X = Zr - i*Zi
            const int a = 128 + 3 * (128 >> 5);       // 140
            orow[128] =  2.0f * sr[a];
            irow[128] = -2.0f * si[a];
        }
    }
}

extern "C" void kernel_launch(void* const* d_in, const int* in_sizes, int n_in,
                              void* d_out, int out_size)
{
    const float* x = (const float*)d_in[0];
    float* out = (float*)d_out;
    float* yre = out;                                  // [32768, 257]
    float* yim = out + (long long)NBATCH * NOUT;       // [32768, 257]

    rfft512_warp<<<NBATCH / RPB, 32 * RPB>>>(x, yre, yim);
}

// round 10
// speedup vs baseline: 1.0702x; 1.0066x over previous
#include <cuda_runtime.h>
#include <math_constants.h>
#include <cstdint>

#define NOUT   257
#define NBATCH 32768
#define RPB    8

__device__ __forceinline__ void cmul(float ar, float ai, float br, float bi,
                                     float& cr, float& ci)
{
    cr = ar * br - ai * bi;
    ci = ar * bi + ai * br;
}

// ---- f32x2 packed helpers (sm_103a native) ----
__device__ __forceinline__ uint64_t pk2(float lo, float hi) {
    uint64_t r;
    asm("mov.b64 %0, {%1, %2};" : "=l"(r) : "f"(lo), "f"(hi));
    return r;
}
__device__ __forceinline__ void upk2(uint64_t v, float& lo, float& hi) {
    asm("mov.b64 {%0, %1}, %2;" : "=f"(lo), "=f"(hi) : "l"(v));
}
__device__ __forceinline__ uint64_t fma2(uint64_t a, uint64_t b, uint64_t c) {
    uint64_t d;
    asm("fma.rn.f32x2 %0, %1, %2, %3;" : "=l"(d) : "l"(a), "l"(b), "l"(c));
    return d;
}
__device__ __forceinline__ uint64_t mul2(uint64_t a, uint64_t b) {
    uint64_t d;
    asm("mul.rn.f32x2 %0, %1, %2;" : "=l"(d) : "l"(a), "l"(b));
    return d;
}

#define ONE2  0x3F8000003F800000ull   // ( 1.0f,  1.0f)
#define NEG2  0xBF800000BF800000ull   // (-1.0f, -1.0f)

// Packed cross-lane DIF stage, butterfly distance H (select-free).
template<int H>
__device__ __forceinline__ void dif_stage_p(uint64_t* Zr, uint64_t* Zi,
                                            uint64_t s2, uint64_t wc2,
                                            uint64_t nws2, uint64_t ws2)
{
    #pragma unroll
    for (int q = 0; q < 4; ++q) {
        const uint64_t orr = __shfl_xor_sync(0xffffffffu, Zr[q], H);
        const uint64_t oii = __shfl_xor_sync(0xffffffffu, Zi[q], H);
        const uint64_t dr = fma2(s2, Zr[q], orr);
        const uint64_t di = fma2(s2, Zi[q], oii);
        Zr[q] = fma2(wc2, dr, mul2(nws2, di));
        Zi[q] = fma2(wc2, di, mul2(ws2,  dr));
    }
}

__global__ __launch_bounds__(256, 6)   // cap regs at 40 -> 6 blocks/SM
void rfft512_warp(const float* __restrict__ x,
                  float* __restrict__ yre,
                  float* __restrict__ yim)
{
    // Z staged as scalars at addr = k + 3*(k>>5): conflict-free scatter/gather.
    __shared__ float ssr[RPB][284];
    __shared__ float ssi[RPB][284];

    const int lane = threadIdx.x & 31;
    const int w    = threadIdx.x >> 5;
    const long long row = (long long)blockIdx.x * RPB + w;
    const float* xr = x + row * 512;
    float* sr = ssr[w];
    float* si = ssi[w];

    // ---- load z[m] = 0.5*(x[2m] + i x[2m+1]), m = lane + 32 r ----
    float zr[8], zi[8];
    #pragma unroll
    for (int r = 0; r < 8; ++r) {
        float2 v = *reinterpret_cast<const float2*>(xr + 2 * (lane + 32 * r));
        zr[r] = 0.5f * v.x; zi[r] = 0.5f * v.y;
    }

    // ---- step A: radix-8 DIF over reg index -> slot r holds k2 = br3(r) ----
    const float C = 0.70710678118654752440f;
    {   // h=4, twiddles W8^{0..3}
        float dr, di;
        dr = zr[0] - zr[4]; di = zi[0] - zi[4];
        zr[0] += zr[4]; zi[0] += zi[4];
        zr[4] = dr; zi[4] = di;

        dr = zr[1] - zr[5]; di = zi[1] - zi[5];
        zr[1] += zr[5]; zi[1] += zi[5];
        zr[5] = C * (dr + di); zi[5] = C * (di - dr);

        dr = zr[2] - zr[6]; di = zi[2] - zi[6];
        zr[2] += zr[6]; zi[2] += zi[6];
        zr[6] = di; zi[6] = -dr;

        dr = zr[3] - zr[7]; di = zi[3] - zi[7];
        zr[3] += zr[7]; zi[3] += zi[7];
        zr[7] = C * (di - dr); zi[7] = -C * (dr + di);
    }
    {   // h=2, twiddles 1, -i
        float dr, di;
        dr = zr[0] - zr[2]; di = zi[0] - zi[2];
        zr[0] += zr[2]; zi[0] += zi[2]; zr[2] = dr; zi[2] = di;

        dr = zr[1] - zr[3]; di = zi[1] - zi[3];
        zr[1] += zr[3]; zi[1] += zi[3]; zr[3] = di; zi[3] = -dr;

        dr = zr[4] - zr[6]; di = zi[4] - zi[6];
        zr[4] += zr[6]; zi[4] += zi[6]; zr[6] = dr; zi[6] = di;

        dr = zr[5] - zr[7]; di = zi[5] - zi[7];
        zr[5] += zr[7]; zi[5] += zi[7]; zr[7] = di; zi[7] = -dr;
    }
    {   // h=1
        float dr, di;
        dr = zr[0] - zr[1]; di = zi[0] - zi[1];
        zr[0] += zr[1]; zi[0] += zi[1]; zr[1] = dr; zi[1] = di;
        dr = zr[2] - zr[3]; di = zi[2] - zi[3];
        zr[2] += zr[3]; zi[2] += zi[3]; zr[3] = dr; zi[3] = di;
        dr = zr[4] - zr[5]; di = zi[4] - zi[5];
        zr[4] += zr[5]; zi[4] += zi[5]; zr[5] = dr; zi[5] = di;
        dr = zr[6] - zr[7]; di = zi[6] - zi[7];
        zr[6] += zr[7]; zi[6] += zi[7]; zr[7] = dr; zi[7] = di;
    }

    // ---- step B: multiply slot (k2) by W_256^{lane * k2} ----
    {
        float w1r, w1i;
        __sincosf(-2.0f * CUDART_PI_F * (float)lane / 256.0f, &w1i, &w1r);
        float w2r, w2i, w3r, w3i, w4r, w4i, w5r, w5i, w6r, w6i, w7r, w7i;
        cmul(w1r, w1i, w1r, w1i, w2r, w2i);
        cmul(w2r, w2i, w1r, w1i, w3r, w3i);
        cmul(w2r, w2i, w2r, w2i, w4r, w4i);
        cmul(w4r, w4i, w1r, w1i, w5r, w5i);
        cmul(w3r, w3i, w3r, w3i, w6r, w6i);
        cmul(w4r, w4i, w3r, w3i, w7r, w7i);

        float tr, ti;
        cmul(zr[1], zi[1], w4r, w4i, tr, ti); zr[1] = tr; zi[1] = ti;  // k2=4
        cmul(zr[2], zi[2], w2r, w2i, tr, ti); zr[2] = tr; zi[2] = ti;  // k2=2
        cmul(zr[3], zi[3], w6r, w6i, tr, ti); zr[3] = tr; zi[3] = ti;  // k2=6
        cmul(zr[4], zi[4], w1r, w1i, tr, ti); zr[4] = tr; zi[4] = ti;  // k2=1
        cmul(zr[5], zi[5], w5r, w5i, tr, ti); zr[5] = tr; zi[5] = ti;  // k2=5
        cmul(zr[6], zi[6], w3r, w3i, tr, ti); zr[6] = tr; zi[6] = ti;  // k2=3
        cmul(zr[7], zi[7], w7r, w7i, tr, ti); zr[7] = tr; zi[7] = ti;  // k2=7
    }

    // ---- step C: 32-pt DIF across lanes, f32x2-packed over reg pairs ----
    {
        float uc, us;   // u = W_32^{lane&15}
        __sincosf(-CUDART_PI_F * (float)(lane & 15) / 16.0f, &us, &uc);
        const float p2c = uc * uc - us * us,     p2s = 2.0f * uc * us;
        const float p4c = p2c * p2c - p2s * p2s, p4s = 2.0f * p2c * p2s;
        const float p8c = p4c * p4c - p4s * p4s, p8s = 2.0f * p4c * p4s;

        uint64_t Zr[4], Zi[4];
        #pragma unroll
        for (int q = 0; q < 4; ++q) {
            Zr[q] = pk2(zr[2 * q], zr[2 * q + 1]);
            Zi[q] = pk2(zi[2 * q], zi[2 * q + 1]);
        }

        {   // H=16: w = u
            const bool hi = (lane & 16) != 0;
            const float wc = hi ?  uc : 1.0f;
            const float ws = hi ?  us : 0.0f;
            dif_stage_p<16>(Zr, Zi, hi ? NEG2 : ONE2,
                            pk2(wc, wc), pk2(-ws, -ws), pk2(ws, ws));
        }
        {   // H=8: w = -u^2
            const bool hi = (lane & 8) != 0;
            const float wc = hi ? -p2c : 1.0f;
            const float ws = hi ? -p2s : 0.0f;
            dif_stage_p<8>(Zr, Zi, hi ? NEG2 : ONE2,
                           pk2(wc, wc), pk2(-ws, -ws), pk2(ws, ws));
        }
        {   // H=4: w = -u^4
            const bool hi = (lane & 4) != 0;
            const float wc = hi ? -p4c : 1.0f;
            const float ws = hi ? -p4s : 0.0f;
            dif_stage_p<4>(Zr, Zi, hi ? NEG2 : ONE2,
                           pk2(wc, wc), pk2(-ws, -ws), pk2(ws, ws));
        }
        {   // H=2: w = -u^8
            const bool hi = (lane & 2) != 0;
            const float wc = hi ? -p8c : 1.0f;
            const float ws = hi ? -p8s : 0.0f;
            dif_stage_p<2>(Zr, Zi, hi ? NEG2 : ONE2,
                           pk2(wc, wc), pk2(-ws, -ws), pk2(ws, ws));
        }
        {   // H=1: w = 1 (twiddle-free)
            const uint64_t s2 = (lane & 1) ? NEG2 : ONE2;
            #pragma unroll
            for (int q = 0; q < 4; ++q) {
                const uint64_t orr = __shfl_xor_sync(0xffffffffu, Zr[q], 1);
                const uint64_t oii = __shfl_xor_sync(0xffffffffu, Zi[q], 1);
                Zr[q] = fma2(s2, Zr[q], orr);
                Zi[q] = fma2(s2, Zi[q], oii);
            }
        }

        #pragma unroll
        for (int q = 0; q < 4; ++q) {
            upk2(Zr[q], zr[2 * q], zr[2 * q + 1]);
            upk2(Zi[q], zi[2 * q], zi[2 * q + 1]);
        }
    }
    // lane l, slot r holds 0.5 * Z[k2 + 8*kappa], k2 = br3(r), kappa = br5(l)

    // ---- stage Z to smem at addr = k + 3*(k>>5)  (conflict-free scatter) ----
    {
        const int kap = __brev((unsigned)lane) >> 27;   // bitrev5(lane)
        const int base = 8 * kap + 3 * (kap >> 2);      // = (8kap) + 3*((8kap)>>5)
        const int K2M[8] = {0, 4, 2, 6, 1, 5, 3, 7};
        #pragma unroll
        for (int r = 0; r < 8; ++r) {
            sr[base + K2M[r]] = zr[r];
            si[base + K2M[r]] = zi[r];
        }
    }
    __syncwarp();

    // ---- pair untangle: k = 32j + lane (j=0..3) gives X[k] AND X[256-k] ----
    float* orow = yre + row * NOUT;
    float* irow = yim + row * NOUT;
    {
        float bc, bs;   // W_512^lane
        __sincosf(-2.0f * CUDART_PI_F * (float)lane / 512.0f, &bs, &bc);

        // W_16^j, j = 0..3
        const float CJ[4] = { 1.0f,  0.92387953251128674f,
                              0.70710678118654757f,  0.38268343236508984f};
        const float SJ[4] = { 0.0f, -0.38268343236508977f,
                             -0.70710678118654746f, -0.92387953251128674f};

        #pragma unroll
        for (int j = 0; j < 4; ++j) {
            const int k  = 32 * j + lane;
            const int ak = k + 3 * (k >> 5);
            const int km = (256 - k) & 255;           // Z partner (wraps k=0 -> 0)
            const int am = km + 3 * (km >> 5);

            const float Zkr = sr[ak], Zki = si[ak];
            const float Zmr = sr[am], Zmi = si[am];

            const float Fer = Zkr + Zmr;
            const float Fei = Zki - Zmi;
            const float For = Zki + Zmi;
            const float Foi = Zmr - Zkr;

            // w = W_512^k = (bc + i bs) * W_16^j
            const float wc = fmaf(bc, CJ[j], -bs * SJ[j]);
            const float ws = fmaf(bc, SJ[j],  bs * CJ[j]);

            const float P = fmaf(wc, For, -ws * Foi);
            const float Q = fmaf(wc, Foi,  ws * For);

            orow[k] = Fer + P;          // X[k]
            irow[k] = Fei + Q;
            orow[256 - k] = Fer - P;    // X[256-k] (k=0 -> bin 256)
            irow[256 - k] = Q - Fei;
        }
        if (lane == 0) {                // self-paired bin 128: X = Zr - i*Zi
            const int a = 128 + 3 * (128 >> 5);       // 140
            orow[128] =  2.0f * sr[a];
            irow[128] = -2.0f * si[a];
        }
    }
}

extern "C" void kernel_launch(void* const* d_in, const int* in_sizes, int n_in,
                              void* d_out, int out_size)
{
    const float* x = (const float*)d_in[0];
    float* out = (float*)d_out;
    float* yre = out;                                  // [32768, 257]
    float* yim = out + (long long)NBATCH * NOUT;       // [32768, 257]

    rfft512_warp<<<NBATCH / RPB, 32 * RPB>>>(x, yre, yim);
}

// round 11
// speedup vs baseline: 1.1231x; 1.0495x over previous
#include <cuda_runtime.h>
#include <math_constants.h>
#include <cstdint>

#define NOUT   257
#define NBATCH 32768
#define RPB    8

__device__ __forceinline__ void cmul(float ar, float ai, float br, float bi,
                                     float& cr, float& ci)
{
    cr = ar * br - ai * bi;
    ci = ar * bi + ai * br;
}

// ---- f32x2 packed helpers (sm_103a native) ----
__device__ __forceinline__ uint64_t pk2(float lo, float hi) {
    uint64_t r;
    asm("mov.b64 %0, {%1, %2};" : "=l"(r) : "f"(lo), "f"(hi));
    return r;
}
__device__ __forceinline__ void upk2(uint64_t v, float& lo, float& hi) {
    asm("mov.b64 {%0, %1}, %2;" : "=f"(lo), "=f"(hi) : "l"(v));
}
__device__ __forceinline__ uint64_t fma2(uint64_t a, uint64_t b, uint64_t c) {
    uint64_t d;
    asm("fma.rn.f32x2 %0, %1, %2, %3;" : "=l"(d) : "l"(a), "l"(b), "l"(c));
    return d;
}
__device__ __forceinline__ uint64_t mul2(uint64_t a, uint64_t b) {
    uint64_t d;
    asm("mul.rn.f32x2 %0, %1, %2;" : "=l"(d) : "l"(a), "l"(b));
    return d;
}

#define ONE2  0x3F8000003F800000ull   // ( 1.0f,  1.0f)
#define NEG2  0xBF800000BF800000ull   // (-1.0f, -1.0f)

// Packed cross-lane DIF stage, butterfly distance H (select-free).
template<int H>
__device__ __forceinline__ void dif_stage_p(uint64_t* Zr, uint64_t* Zi,
                                            uint64_t s2, uint64_t wc2,
                                            uint64_t nws2, uint64_t ws2)
{
    #pragma unroll
    for (int q = 0; q < 4; ++q) {
        const uint64_t orr = __shfl_xor_sync(0xffffffffu, Zr[q], H);
        const uint64_t oii = __shfl_xor_sync(0xffffffffu, Zi[q], H);
        const uint64_t dr = fma2(s2, Zr[q], orr);
        const uint64_t di = fma2(s2, Zi[q], oii);
        Zr[q] = fma2(wc2, dr, mul2(nws2, di));
        Zi[q] = fma2(wc2, di, mul2(ws2,  dr));
    }
}

__global__ __launch_bounds__(256)
void rfft512_warp(const float* __restrict__ x,
                  float* __restrict__ yre,
                  float* __restrict__ yim)
{
    // Z staged interleaved (re,im) at float2 addr a = k + 3*(k>>5).
    __shared__ float2 ssz[RPB][288];

    const int lane = threadIdx.x & 31;
    const int w    = threadIdx.x >> 5;
    const long long row = (long long)blockIdx.x * RPB + w;
    const float* xr = x + row * 512;
    float2* sz = ssz[w];

    // ---- load z[m] = 0.5*(x[2m] + i x[2m+1]), m = lane + 32 r ----
    float zr[8], zi[8];
    #pragma unroll
    for (int r = 0; r < 8; ++r) {
        float2 v = *reinterpret_cast<const float2*>(xr + 2 * (lane + 32 * r));
        zr[r] = 0.5f * v.x; zi[r] = 0.5f * v.y;
    }

    // ---- step A: radix-8 DIF over reg index -> slot r holds k2 = br3(r) ----
    const float C = 0.70710678118654752440f;
    {   // h=4, twiddles W8^{0..3}
        float dr, di;
        dr = zr[0] - zr[4]; di = zi[0] - zi[4];
        zr[0] += zr[4]; zi[0] += zi[4];
        zr[4] = dr; zi[4] = di;

        dr = zr[1] - zr[5]; di = zi[1] - zi[5];
        zr[1] += zr[5]; zi[1] += zi[5];
        zr[5] = C * (dr + di); zi[5] = C * (di - dr);

        dr = zr[2] - zr[6]; di = zi[2] - zi[6];
        zr[2] += zr[6]; zi[2] += zi[6];
        zr[6] = di; zi[6] = -dr;

        dr = zr[3] - zr[7]; di = zi[3] - zi[7];
        zr[3] += zr[7]; zi[3] += zi[7];
        zr[7] = C * (di - dr); zi[7] = -C * (dr + di);
    }
    {   // h=2, twiddles 1, -i
        float dr, di;
        dr = zr[0] - zr[2]; di = zi[0] - zi[2];
        zr[0] += zr[2]; zi[0] += zi[2]; zr[2] = dr; zi[2] = di;

        dr = zr[1] - zr[3]; di = zi[1] - zi[3];
        zr[1] += zr[3]; zi[1] += zi[3]; zr[3] = di; zi[3] = -dr;

        dr = zr[4] - zr[6]; di = zi[4] - zi[6];
        zr[4] += zr[6]; zi[4] += zi[6]; zr[6] = dr; zi[6] = di;

        dr = zr[5] - zr[7]; di = zi[5] - zi[7];
        zr[5] += zr[7]; zi[5] += zi[7]; zr[7] = di; zi[7] = -dr;
    }
    {   // h=1
        float dr, di;
        dr = zr[0] - zr[1]; di = zi[0] - zi[1];
        zr[0] += zr[1]; zi[0] += zi[1]; zr[1] = dr; zi[1] = di;
        dr = zr[2] - zr[3]; di = zi[2] - zi[3];
        zr[2] += zr[3]; zi[2] += zi[3]; zr[3] = dr; zi[3] = di;
        dr = zr[4] - zr[5]; di = zi[4] - zi[5];
        zr[4] += zr[5]; zi[4] += zi[5]; zr[5] = dr; zi[5] = di;
        dr = zr[6] - zr[7]; di = zi[6] - zi[7];
        zr[6] += zr[7]; zi[6] += zi[7]; zr[7] = dr; zi[7] = di;
    }

    // ---- step B: multiply slot (k2) by W_256^{lane * k2} ----
    {
        float w1r, w1i;
        __sincosf(-2.0f * CUDART_PI_F * (float)lane / 256.0f, &w1i, &w1r);
        float w2r, w2i, w3r, w3i, w4r, w4i, w5r, w5i, w6r, w6i, w7r, w7i;
        cmul(w1r, w1i, w1r, w1i, w2r, w2i);
        cmul(w2r, w2i, w1r, w1i, w3r, w3i);
        cmul(w2r, w2i, w2r, w2i, w4r, w4i);
        cmul(w4r, w4i, w1r, w1i, w5r, w5i);
        cmul(w3r, w3i, w3r, w3i, w6r, w6i);
        cmul(w4r, w4i, w3r, w3i, w7r, w7i);

        float tr, ti;
        cmul(zr[1], zi[1], w4r, w4i, tr, ti); zr[1] = tr; zi[1] = ti;  // k2=4
        cmul(zr[2], zi[2], w2r, w2i, tr, ti); zr[2] = tr; zi[2] = ti;  // k2=2
        cmul(zr[3], zi[3], w6r, w6i, tr, ti); zr[3] = tr; zi[3] = ti;  // k2=6
        cmul(zr[4], zi[4], w1r, w1i, tr, ti); zr[4] = tr; zi[4] = ti;  // k2=1
        cmul(zr[5], zi[5], w5r, w5i, tr, ti); zr[5] = tr; zi[5] = ti;  // k2=5
        cmul(zr[6], zi[6], w3r, w3i, tr, ti); zr[6] = tr; zi[6] = ti;  // k2=3
        cmul(zr[7], zi[7], w7r, w7i, tr, ti); zr[7] = tr; zi[7] = ti;  // k2=7
    }

    // ---- step C: 32-pt DIF across lanes, f32x2-packed over reg pairs ----
    {
        float uc, us;   // u = W_32^{lane&15}
        __sincosf(-CUDART_PI_F * (float)(lane & 15) / 16.0f, &us, &uc);
        const float p2c = uc * uc - us * us,     p2s = 2.0f * uc * us;
        const float p4c = p2c * p2c - p2s * p2s, p4s = 2.0f * p2c * p2s;
        const float p8c = p4c * p4c - p4s * p4s, p8s = 2.0f * p4c * p4s;

        uint64_t Zr[4], Zi[4];
        #pragma unroll
        for (int q = 0; q < 4; ++q) {
            Zr[q] = pk2(zr[2 * q], zr[2 * q + 1]);
            Zi[q] = pk2(zi[2 * q], zi[2 * q + 1]);
        }

        {   // H=16: w = u
            const bool hi = (lane & 16) != 0;
            const float wc = hi ?  uc : 1.0f;
            const float ws = hi ?  us : 0.0f;
            dif_stage_p<16>(Zr, Zi, hi ? NEG2 : ONE2,
                            pk2(wc, wc), pk2(-ws, -ws), pk2(ws, ws));
        }
        {   // H=8: w = -u^2
            const bool hi = (lane & 8) != 0;
            const float wc = hi ? -p2c : 1.0f;
            const float ws = hi ? -p2s : 0.0f;
            dif_stage_p<8>(Zr, Zi, hi ? NEG2 : ONE2,
                           pk2(wc, wc), pk2(-ws, -ws), pk2(ws, ws));
        }
        {   // H=4: w = -u^4
            const bool hi = (lane & 4) != 0;
            const float wc = hi ? -p4c : 1.0f;
            const float ws = hi ? -p4s : 0.0f;
            dif_stage_p<4>(Zr, Zi, hi ? NEG2 : ONE2,
                           pk2(wc, wc), pk2(-ws, -ws), pk2(ws, ws));
        }
        {   // H=2: w = -u^8
            const bool hi = (lane & 2) != 0;
            const float wc = hi ? -p8c : 1.0f;
            const float ws = hi ? -p8s : 0.0f;
            dif_stage_p<2>(Zr, Zi, hi ? NEG2 : ONE2,
                           pk2(wc, wc), pk2(-ws, -ws), pk2(ws, ws));
        }
        {   // H=1: w = 1 (twiddle-free)
            const uint64_t s2 = (lane & 1) ? NEG2 : ONE2;
            #pragma unroll
            for (int q = 0; q < 4; ++q) {
                const uint64_t orr = __shfl_xor_sync(0xffffffffu, Zr[q], 1);
                const uint64_t oii = __shfl_xor_sync(0xffffffffu, Zi[q], 1);
                Zr[q] = fma2(s2, Zr[q], orr);
                Zi[q] = fma2(s2, Zi[q], oii);
            }
        }

        #pragma unroll
        for (int q = 0; q < 4; ++q) {
            upk2(Zr[q], zr[2 * q], zr[2 * q + 1]);
            upk2(Zi[q], zi[2 * q], zi[2 * q + 1]);
        }
    }
    // lane l, slot r holds 0.5 * Z[k2 + 8*kappa], k2 = br3(r), kappa = br5(l)

    // ---- stage Z to smem (interleaved) at a = k + 3*(k>>5) ----
    {
        const int kap = __brev((unsigned)lane) >> 27;   // bitrev5(lane)
        const int base = 8 * kap + 3 * (kap >> 2);      // = (8kap) + 3*((8kap)>>5)
        const int K2M[8] = {0, 4, 2, 6, 1, 5, 3, 7};
        #pragma unroll
        for (int r = 0; r < 8; ++r)
            sz[base + K2M[r]] = make_float2(zr[r], zi[r]);
    }
    __syncwarp();

    // ---- pair untangle: k = 32j + lane (j=0..3) gives X[k] AND X[256-k] ----
    float* orow = yre + row * NOUT;
    float* irow = yim + row * NOUT;
    {
        float bc, bs;   // W_512^lane
        __sincosf(-2.0f * CUDART_PI_F * (float)lane / 512.0f, &bs, &bc);

        // W_16^j, j = 0..3
        const float CJ[4] = { 1.0f,  0.92387953251128674f,
                              0.70710678118654757f,  0.38268343236508984f};
        const float SJ[4] = { 0.0f, -0.38268343236508977f,
                             -0.70710678118654746f, -0.92387953251128674f};

        #pragma unroll
        for (int j = 0; j < 4; ++j) {
            const int k  = 32 * j + lane;
            const int km = (256 - k) & 255;           // Z partner (wraps k=0 -> 0)

            const float2 Zk = sz[k + 3 * (k >> 5)];
            const float2 Zm = sz[km + 3 * (km >> 5)];

            const float Fer = Zk.x + Zm.x;
            const float Fei = Zk.y - Zm.y;
            const float For = Zk.y + Zm.y;
            const float Foi = Zm.x - Zk.x;

            // w = W_512^k = (bc + i bs) * W_16^j
            const float wc = fmaf(bc, CJ[j], -bs * SJ[j]);
            const float ws = fmaf(bc, SJ[j],  bs * CJ[j]);

            const float P = fmaf(wc, For, -ws * Foi);
            const float Q = fmaf(wc, Foi,  ws * For);

            orow[k] = Fer + P;          // X[k]
            irow[k] = Fei + Q;
            orow[256 - k] = Fer - P;    // X[256-k] (k=0 -> bin 256)
            irow[256 - k] = Q - Fei;
        }
        if (lane == 0) {                // self-paired bin 128: X = Zr - i*Zi
            const float2 Zc = sz[128 + 3 * (128 >> 5)];
            orow[128] =  2.0f * Zc.x;
            irow[128] = -2.0f * Zc.y;
        }
    }
}

extern "C" void kernel_launch(void* const* d_in, const int* in_sizes, int n_in,
                              void* d_out, int out_size)
{
    const float* x = (const float*)d_in[0];
    float* out = (float*)d_out;
    float* yre = out;                                  // [32768, 257]
    float* yim = out + (long long)NBATCH * NOUT;       // [32768, 257]

    rfft512_warp<<<NBATCH / RPB, 32 * RPB>>>(x, yre, yim);
}